// round 3
// baseline (speedup 1.0000x reference)
#include <cuda_runtime.h>
#include <cuda_bf16.h>

// Problem constants
#define BDIM   128
#define NDIM   32
#define DDIM   256
#define HDIM   1024
#define HC     64
#define NCHUNK 16
#define THREADS 128

// smem strides (in 32-bit words), padded for conflict-free mma fragment access
#define PS_STRIDE 260   // 260 % 32 == 4  -> bank = 4*gid + tig (distinct)
#define W1_STRIDE 72    // 72  % 32 == 8  -> bank = 8*tig + gid (distinct)
#define W2_STRIDE 264   // 264 % 32 == 8
#define HS_STRIDE 68    // 68  % 32 == 4

// smem layout (bytes)
#define SMEM_XS 0                       // float [32][256]        = 32768
#define SMEM_PS 32768                   // tf32  [32][260]        = 33280
#define SMEM_W1 66048                   // tf32  [256][72]        = 73728
#define SMEM_W2 139776                  // tf32  [64][264]        = 67584
#define SMEM_HS 207360                  // tf32  [2][32][68]      = 17408
#define SMEM_TOTAL 224768               // < 227KB opt-in limit

__device__ __forceinline__ unsigned f2tf(float x) {
    unsigned u;
    asm("cvt.rna.tf32.f32 %0, %1;" : "=r"(u) : "f"(x));
    return u;
}

__device__ __forceinline__ void mma_tf32(float d[4], const unsigned a[4],
                                         unsigned b0, unsigned b1) {
    asm volatile(
        "mma.sync.aligned.m16n8k8.row.col.f32.tf32.tf32.f32 "
        "{%0,%1,%2,%3}, {%4,%5,%6,%7}, {%8,%9}, {%0,%1,%2,%3};\n"
        : "+f"(d[0]), "+f"(d[1]), "+f"(d[2]), "+f"(d[3])
        : "r"(a[0]), "r"(a[1]), "r"(a[2]), "r"(a[3]), "r"(b0), "r"(b1));
}

__global__ __launch_bounds__(THREADS, 1)
void fused_pair_mlp_kernel(const float* __restrict__ X,
                           const float* __restrict__ W1g,
                           const float* __restrict__ b1g,
                           const float* __restrict__ W2g,
                           const float* __restrict__ b2g,
                           float* __restrict__ out) {
    extern __shared__ unsigned char smem[];
    float*    Xs  = reinterpret_cast<float*>(smem + SMEM_XS);
    unsigned* Ps  = reinterpret_cast<unsigned*>(smem + SMEM_PS);
    unsigned* W1s = reinterpret_cast<unsigned*>(smem + SMEM_W1);
    unsigned* W2s = reinterpret_cast<unsigned*>(smem + SMEM_W2);
    unsigned* Hs  = reinterpret_cast<unsigned*>(smem + SMEM_HS);

    const int b    = blockIdx.x;
    const int tid  = threadIdx.x;
    const int w    = tid >> 5;      // warp 0..3
    const int lane = tid & 31;
    const int gid  = lane >> 2;     // 0..7
    const int tig  = lane & 3;      // 0..3

    // ---- stage X_b [32,256] fp32 into smem (reused by all 32 i-iters x 16 chunks)
    {
        const float4* xg  = reinterpret_cast<const float4*>(X + (size_t)b * NDIM * DDIM);
        float4*       xs4 = reinterpret_cast<float4*>(Xs);
        #pragma unroll
        for (int q = tid; q < NDIM * DDIM / 4; q += THREADS) xs4[q] = xg[q];
    }

    // persistent output accumulator: this warp owns out cols [64w, 64w+64)
    float oacc[2][8][4];
    #pragma unroll
    for (int m = 0; m < 2; ++m)
        #pragma unroll
        for (int t = 0; t < 8; ++t)
            #pragma unroll
            for (int r = 0; r < 4; ++r) oacc[m][t][r] = 0.f;

    for (int c = 0; c < NCHUNK; ++c) {
        __syncthreads();  // protect W1s/W2s overwrite vs previous chunk's readers

        // ---- stage W1 chunk [256, 64] (cols c*64..) as tf32, stride 72
        #pragma unroll 4
        for (int q = tid; q < 4096; q += THREADS) {
            int d = q >> 4, f = q & 15;
            float4 v = *reinterpret_cast<const float4*>(W1g + (size_t)d * HDIM + c * HC + f * 4);
            uint4 u = make_uint4(f2tf(v.x), f2tf(v.y), f2tf(v.z), f2tf(v.w));
            *reinterpret_cast<uint4*>(W1s + d * W1_STRIDE + f * 4) = u;
        }
        // ---- stage W2 chunk [64, 256] (rows c*64..) as tf32, stride 264
        #pragma unroll 4
        for (int q = tid; q < 4096; q += THREADS) {
            int h = q >> 6, f = q & 63;
            float4 v = *reinterpret_cast<const float4*>(W2g + (size_t)(c * HC + h) * DDIM + f * 4);
            uint4 u = make_uint4(f2tf(v.x), f2tf(v.y), f2tf(v.z), f2tf(v.w));
            *reinterpret_cast<uint4*>(W2s + h * W2_STRIDE + f * 4) = u;
        }
        // per-thread bias values for this warp's 16 h-cols (2 n-tiles)
        const float bias00 = __ldg(b1g + c * HC + 16 * w + 2 * tig);
        const float bias01 = __ldg(b1g + c * HC + 16 * w + 2 * tig + 1);
        const float bias10 = __ldg(b1g + c * HC + 16 * w + 8 + 2 * tig);
        const float bias11 = __ldg(b1g + c * HC + 16 * w + 8 + 2 * tig + 1);
        __syncthreads();  // W chunk ready

        for (int i = 0; i < NDIM; ++i) {
            // ---- build P_i[j,d] = x[i,d] * x[j,d], tf32, stride 260
            {
                const float4* xi4 = reinterpret_cast<const float4*>(Xs + i * DDIM);
                const float4* xs4 = reinterpret_cast<const float4*>(Xs);
                #pragma unroll 4
                for (int q = tid; q < NDIM * DDIM / 4; q += THREADS) {
                    int j = q >> 6, d4 = q & 63;
                    float4 a  = xs4[j * 64 + d4];
                    float4 bb = xi4[d4];
                    uint4 u = make_uint4(f2tf(a.x * bb.x), f2tf(a.y * bb.y),
                                         f2tf(a.z * bb.z), f2tf(a.w * bb.w));
                    *reinterpret_cast<uint4*>(Ps + j * PS_STRIDE + d4 * 4) = u;
                }
            }
            __syncthreads();  // P ready (also: everyone finished GEMM2 of i-1)

            // ---- GEMM1: h[32, 16w..16w+16) = P[32,256] @ W1s[:, 16w..], K=256
            float hacc[2][2][4];
            #pragma unroll
            for (int m = 0; m < 2; ++m)
                #pragma unroll
                for (int t = 0; t < 2; ++t)
                    #pragma unroll
                    for (int r = 0; r < 4; ++r) hacc[m][t][r] = 0.f;
            {
                const unsigned* pa = Ps  + gid * PS_STRIDE + tig;
                const unsigned* pb = W1s + tig * W1_STRIDE + 16 * w + gid;
                #pragma unroll 4
                for (int kk = 0; kk < 32; ++kk) {
                    const int k0 = kk * 8;
                    unsigned A0[4], A1[4];
                    A0[0] = pa[k0];
                    A0[1] = pa[8  * PS_STRIDE + k0];
                    A0[2] = pa[k0 + 4];
                    A0[3] = pa[8  * PS_STRIDE + k0 + 4];
                    A1[0] = pa[16 * PS_STRIDE + k0];
                    A1[1] = pa[24 * PS_STRIDE + k0];
                    A1[2] = pa[16 * PS_STRIDE + k0 + 4];
                    A1[3] = pa[24 * PS_STRIDE + k0 + 4];
                    unsigned B00 = pb[k0 * W1_STRIDE];
                    unsigned B01 = pb[(k0 + 4) * W1_STRIDE];
                    unsigned B10 = pb[k0 * W1_STRIDE + 8];
                    unsigned B11 = pb[(k0 + 4) * W1_STRIDE + 8];
                    mma_tf32(hacc[0][0], A0, B00, B01);
                    mma_tf32(hacc[1][0], A1, B00, B01);
                    mma_tf32(hacc[0][1], A0, B10, B11);
                    mma_tf32(hacc[1][1], A1, B10, B11);
                }
            }

            // ---- bias + relu, store h tile to double-buffered smem (tf32)
            unsigned* Hb = Hs + (i & 1) * (NDIM * HS_STRIDE);
            #pragma unroll
            for (int m = 0; m < 2; ++m) {
                #pragma unroll
                for (int t = 0; t < 2; ++t) {
                    const int col = 16 * w + 8 * t + 2 * tig;
                    const float be = (t ? bias10 : bias00);
                    const float bo = (t ? bias11 : bias01);
                    float f0 = fmaxf(hacc[m][t][0] + be, 0.f);
                    float f1 = fmaxf(hacc[m][t][1] + bo, 0.f);
                    float f2 = fmaxf(hacc[m][t][2] + be, 0.f);
                    float f3 = fmaxf(hacc[m][t][3] + bo, 0.f);
                    const int r = 16 * m + gid;
                    uint2 u01 = make_uint2(f2tf(f0), f2tf(f1));
                    uint2 u23 = make_uint2(f2tf(f2), f2tf(f3));
                    *reinterpret_cast<uint2*>(Hb + r * HS_STRIDE + col)       = u01;
                    *reinterpret_cast<uint2*>(Hb + (r + 8) * HS_STRIDE + col) = u23;
                }
            }
            __syncthreads();  // h tile ready for all warps

            // ---- GEMM2: oacc[32, 64w..] += h[32,64] @ W2s[64, 64w..], K=64
            {
                const unsigned* pa = Hb  + gid * HS_STRIDE + tig;
                const unsigned* pb = W2s + tig * W2_STRIDE + 64 * w + gid;
                #pragma unroll
                for (int kk = 0; kk < 8; ++kk) {
                    const int k0 = kk * 8;
                    unsigned A0[4], A1[4];
                    A0[0] = pa[k0];
                    A0[1] = pa[8  * HS_STRIDE + k0];
                    A0[2] = pa[k0 + 4];
                    A0[3] = pa[8  * HS_STRIDE + k0 + 4];
                    A1[0] = pa[16 * HS_STRIDE + k0];
                    A1[1] = pa[24 * HS_STRIDE + k0];
                    A1[2] = pa[16 * HS_STRIDE + k0 + 4];
                    A1[3] = pa[24 * HS_STRIDE + k0 + 4];
                    #pragma unroll
                    for (int t = 0; t < 8; ++t) {
                        unsigned B0 = pb[k0 * W2_STRIDE + 8 * t];
                        unsigned B1 = pb[(k0 + 4) * W2_STRIDE + 8 * t];
                        mma_tf32(oacc[0][t], A0, B0, B1);
                        mma_tf32(oacc[1][t], A1, B0, B1);
                    }
                }
            }
            // no trailing sync needed: next P-build is guarded by the post-build
            // sync, and Hs is double-buffered by i-parity.
        }
    }

    // ---- epilogue: out[b,j,d] = oacc + 32*b2[d]  (b2 added per-i, summed over 32 i)
    float* og = out + (size_t)b * NDIM * DDIM;
    #pragma unroll
    for (int t = 0; t < 8; ++t) {
        const int col = 64 * w + 8 * t + 2 * tig;
        const float bb0 = 32.0f * __ldg(b2g + col);
        const float bb1 = 32.0f * __ldg(b2g + col + 1);
        #pragma unroll
        for (int m = 0; m < 2; ++m) {
            const int r = 16 * m + gid;
            float2 v0 = make_float2(oacc[m][t][0] + bb0, oacc[m][t][1] + bb1);
            float2 v1 = make_float2(oacc[m][t][2] + bb0, oacc[m][t][3] + bb1);
            *reinterpret_cast<float2*>(og + (size_t)r * DDIM + col)       = v0;
            *reinterpret_cast<float2*>(og + (size_t)(r + 8) * DDIM + col) = v1;
        }
    }
}

extern "C" void kernel_launch(void* const* d_in, const int* in_sizes, int n_in,
                              void* d_out, int out_size) {
    (void)in_sizes; (void)n_in; (void)out_size;
    const float* X  = (const float*)d_in[0];   // [128,32,256]
    const float* W1 = (const float*)d_in[1];   // [256,1024]
    const float* b1 = (const float*)d_in[2];   // [1024]
    const float* W2 = (const float*)d_in[3];   // [1024,256]
    const float* b2 = (const float*)d_in[4];   // [256]
    float* out = (float*)d_out;                // [128,32,256]

    cudaFuncSetAttribute(fused_pair_mlp_kernel,
                         cudaFuncAttributeMaxDynamicSharedMemorySize, SMEM_TOTAL);
    fused_pair_mlp_kernel<<<BDIM, THREADS, SMEM_TOTAL>>>(X, W1, b1, W2, b2, out);
}

// round 5
// speedup vs baseline: 3.2274x; 3.2274x over previous
#include <cuda_runtime.h>
#include <cuda_fp16.h>
#include <cstdint>

#define NDIM   32
#define DDIM   256
#define HDIM   1024
#define HC     128
#define NCHUNK 8
#define THREADS 256

// smem row strides in halves; all rows = 4 mod 32 (words) -> conflict-free ldmatrix
#define PS_H 264
#define W1_H 136
#define W2_H 264
#define HS_H 136

// byte offsets
#define SMEM_XS   0          // float [32][256]            = 32768
#define SMEM_PS   32768      // half  [2 groups][32][264]  = 2*16896
#define PS_BYTES  16896
#define SMEM_W1   66560      // half  [256][136]           = 69632
#define SMEM_W2   136192     // half  [128][264]           = 67584
#define SMEM_HS   203776     // half  [2 groups][32][136]  = 2*8704
#define HS_BYTES  8704
#define SMEM_TOTAL 221184    // < 227KB opt-in

__device__ __forceinline__ unsigned smem_u32(const void* p) {
    unsigned a;
    asm("{ .reg .u64 t; cvta.to.shared.u64 t, %1; cvt.u32.u64 %0, t; }" : "=r"(a) : "l"(p));
    return a;
}
__device__ __forceinline__ void ldsm4(unsigned r[4], unsigned a) {
    asm volatile("ldmatrix.sync.aligned.m8n8.x4.shared.b16 {%0,%1,%2,%3}, [%4];\n"
                 : "=r"(r[0]), "=r"(r[1]), "=r"(r[2]), "=r"(r[3]) : "r"(a));
}
__device__ __forceinline__ void ldsm4t(unsigned r[4], unsigned a) {
    asm volatile("ldmatrix.sync.aligned.m8n8.x4.trans.shared.b16 {%0,%1,%2,%3}, [%4];\n"
                 : "=r"(r[0]), "=r"(r[1]), "=r"(r[2]), "=r"(r[3]) : "r"(a));
}
__device__ __forceinline__ void mma16816(float d[4], const unsigned a[4],
                                         unsigned b0, unsigned b1) {
    asm volatile("mma.sync.aligned.m16n8k16.row.col.f32.f16.f16.f32 "
                 "{%0,%1,%2,%3}, {%4,%5,%6,%7}, {%8,%9}, {%0,%1,%2,%3};\n"
                 : "+f"(d[0]), "+f"(d[1]), "+f"(d[2]), "+f"(d[3])
                 : "r"(a[0]), "r"(a[1]), "r"(a[2]), "r"(a[3]), "r"(b0), "r"(b1));
}

__global__ __launch_bounds__(THREADS, 1)
void fused_pair_mlp_fp16(const float* __restrict__ X,  const float* __restrict__ W1g,
                         const float* __restrict__ b1g, const float* __restrict__ W2g,
                         const float* __restrict__ b2g, float* __restrict__ out)
{
    extern __shared__ unsigned char smem[];
    float* Xs = (float*)(smem + SMEM_XS);

    const int b = blockIdx.x, tid = threadIdx.x;
    const int w = tid >> 5, lane = tid & 31;
    const int g = w >> 2;        // group 0: warps 0-3 (tids 0-127), group 1: warps 4-7
    const int wg = w & 3;        // warp-in-group
    const int gid = lane >> 2, tig = lane & 3;
    const int gtid = tid & 127;  // thread-in-group

    __half* Psp = (__half*)(smem + SMEM_PS + g * PS_BYTES);
    __half* W1p = (__half*)(smem + SMEM_W1);
    __half* W2p = (__half*)(smem + SMEM_W2);
    __half* Hsp = (__half*)(smem + SMEM_HS + g * HS_BYTES);

    // stage X_b [32,256] fp32 (reused by all P-builds)
    {
        const float4* xg = (const float4*)(X + (size_t)b * NDIM * DDIM);
        float4* xs4 = (float4*)Xs;
        #pragma unroll
        for (int q = tid; q < NDIM * DDIM / 4; q += THREADS) xs4[q] = xg[q];
    }

    // ldmatrix per-lane address components (canonical x4 layout)
    const int mat  = lane >> 3, mr = lane & 7;
    const int lrow = (mat & 1) * 8 + mr;   // m-row (A) or k-row (B.trans) within 16
    const int kh   = (mat >> 1) * 8;       // k-offset (A) or n-offset (B.trans) in halves

    const unsigned aA_base  = smem_u32(Psp) + (unsigned)(lrow * PS_H + kh) * 2u;
    const unsigned aB1_base = smem_u32(W1p) + (unsigned)(lrow * W1_H + 32 * wg + kh) * 2u;
    const unsigned aHA_base = smem_u32(Hsp) + (unsigned)(lrow * HS_H + kh) * 2u;
    const unsigned aB2_base = smem_u32(W2p) + (unsigned)(lrow * W2_H + 64 * wg + kh) * 2u;

    // persistent out accumulator: warp owns cols [64wg, 64wg+64), group's i-subset
    float oacc[2][8][4];
    #pragma unroll
    for (int m = 0; m < 2; ++m)
        #pragma unroll
        for (int t = 0; t < 8; ++t)
            #pragma unroll
            for (int r = 0; r < 4; ++r) oacc[m][t][r] = 0.f;

    for (int c = 0; c < NCHUNK; ++c) {
        __syncthreads();  // all readers of previous W chunk done

        // stage W1 chunk [256 x 128] -> half (coalesced rows)
        for (int q = tid; q < 8192; q += THREADS) {
            int d = q >> 5, f = q & 31;
            float4 v = *(const float4*)(W1g + (size_t)d * HDIM + c * HC + f * 4);
            __half2 h01 = __floats2half2_rn(v.x, v.y);
            __half2 h23 = __floats2half2_rn(v.z, v.w);
            uint2 u = make_uint2(*(unsigned*)&h01, *(unsigned*)&h23);
            *(uint2*)(W1p + d * W1_H + f * 4) = u;
        }
        // stage W2 chunk [128 x 256] -> half
        for (int q = tid; q < 8192; q += THREADS) {
            int h = q >> 6, f = q & 63;
            float4 v = *(const float4*)(W2g + (size_t)(c * HC + h) * DDIM + f * 4);
            __half2 h01 = __floats2half2_rn(v.x, v.y);
            __half2 h23 = __floats2half2_rn(v.z, v.w);
            uint2 u = make_uint2(*(unsigned*)&h01, *(unsigned*)&h23);
            *(uint2*)(W2p + h * W2_H + f * 4) = u;
        }
        float b1v[4][2];
        #pragma unroll
        for (int t = 0; t < 4; ++t) {
            b1v[t][0] = __ldg(b1g + c * HC + 32 * wg + 8 * t + 2 * tig);
            b1v[t][1] = __ldg(b1g + c * HC + 32 * wg + 8 * t + 2 * tig + 1);
        }
        __syncthreads();  // W chunk ready

        for (int ii = 0; ii < 16; ++ii) {
            const int i = 2 * ii + g;   // group-private i stream

            // ---- build P_i[j,d] = x[j,d]*x[i,d] (fp32 mul, single rounding to half)
            {
                const float4* xs4 = (const float4*)Xs;
                const float4* xi4 = (const float4*)(Xs + i * DDIM);
                #pragma unroll 4
                for (int q = gtid; q < 2048; q += 128) {
                    int j = q >> 6, d4 = q & 63;
                    float4 a  = xs4[j * 64 + d4];
                    float4 xv = xi4[d4];
                    __half2 p01 = __floats2half2_rn(a.x * xv.x, a.y * xv.y);
                    __half2 p23 = __floats2half2_rn(a.z * xv.z, a.w * xv.w);
                    uint2 u = make_uint2(*(unsigned*)&p01, *(unsigned*)&p23);
                    *(uint2*)(Psp + j * PS_H + d4 * 4) = u;
                }
            }
            asm volatile("bar.sync %0, %1;" :: "r"(1 + g), "r"(128));  // P ready; Hs(prev) drained

            // ---- GEMM1: h[32, 32wg..+32] = P[32,256] @ W1[256, chunk], K=256
            float hacc[2][4][4];
            #pragma unroll
            for (int m = 0; m < 2; ++m)
                #pragma unroll
                for (int t = 0; t < 4; ++t)
                    #pragma unroll
                    for (int r = 0; r < 4; ++r) hacc[m][t][r] = 0.f;
            #pragma unroll 4
            for (int kk = 0; kk < 16; ++kk) {
                unsigned A0[4], A1[4], B[8];
                unsigned ak = aA_base + (unsigned)(kk * 32);
                ldsm4(A0, ak);
                ldsm4(A1, ak + (unsigned)(16 * PS_H * 2));
                unsigned bk = aB1_base + (unsigned)(kk * 16 * W1_H * 2);
                ldsm4t(B, bk);          // n-tiles 0,1
                ldsm4t(B + 4, bk + 32); // n-tiles 2,3
                #pragma unroll
                for (int t = 0; t < 4; ++t) {
                    mma16816(hacc[0][t], A0, B[2 * t], B[2 * t + 1]);
                    mma16816(hacc[1][t], A1, B[2 * t], B[2 * t + 1]);
                }
            }

            // ---- bias + relu -> Hs (half)
            #pragma unroll
            for (int m = 0; m < 2; ++m) {
                #pragma unroll
                for (int t = 0; t < 4; ++t) {
                    int col = 32 * wg + 8 * t + 2 * tig;
                    float f0 = fmaxf(hacc[m][t][0] + b1v[t][0], 0.f);
                    float f1 = fmaxf(hacc[m][t][1] + b1v[t][1], 0.f);
                    float f2 = fmaxf(hacc[m][t][2] + b1v[t][0], 0.f);
                    float f3 = fmaxf(hacc[m][t][3] + b1v[t][1], 0.f);
                    int r0 = 16 * m + gid;
                    *(__half2*)(Hsp + r0 * HS_H + col)       = __floats2half2_rn(f0, f1);
                    *(__half2*)(Hsp + (r0 + 8) * HS_H + col) = __floats2half2_rn(f2, f3);
                }
            }
            asm volatile("bar.sync %0, %1;" :: "r"(1 + g), "r"(128));  // Hs ready

            // ---- GEMM2: oacc[32, 64wg..] += h[32,128] @ W2[128,256], K=128
            #pragma unroll 2
            for (int kk = 0; kk < 8; ++kk) {
                unsigned A0[4], A1[4], Bb[16];
                unsigned ak = aHA_base + (unsigned)(kk * 32);
                ldsm4(A0, ak);
                ldsm4(A1, ak + (unsigned)(16 * HS_H * 2));
                unsigned bk = aB2_base + (unsigned)(kk * 16 * W2_H * 2);
                ldsm4t(Bb,      bk);
                ldsm4t(Bb + 4,  bk + 32);
                ldsm4t(Bb + 8,  bk + 64);
                ldsm4t(Bb + 12, bk + 96);
                #pragma unroll
                for (int t = 0; t < 8; ++t) {
                    mma16816(oacc[0][t], A0, Bb[2 * t], Bb[2 * t + 1]);
                    mma16816(oacc[1][t], A1, Bb[2 * t], Bb[2 * t + 1]);
                }
            }
        }
    }

    // ---- epilogue: cross-group reduce via smem (Xs dead), add 32*b2, write out
    __syncthreads();
    float* Os = (float*)(smem + SMEM_XS);
    if (g == 1) {
        #pragma unroll
        for (int t = 0; t < 8; ++t) {
            int col = 64 * wg + 8 * t + 2 * tig;
            #pragma unroll
            for (int m = 0; m < 2; ++m) {
                int r0 = 16 * m + gid;
                *(float2*)(Os + r0 * DDIM + col)       = make_float2(oacc[m][t][0], oacc[m][t][1]);
                *(float2*)(Os + (r0 + 8) * DDIM + col) = make_float2(oacc[m][t][2], oacc[m][t][3]);
            }
        }
    }
    __syncthreads();
    if (g == 0) {
        float* og = out + (size_t)b * NDIM * DDIM;
        #pragma unroll
        for (int t = 0; t < 8; ++t) {
            int col = 64 * wg + 8 * t + 2 * tig;
            float bb0 = 32.0f * __ldg(b2g + col);
            float bb1 = 32.0f * __ldg(b2g + col + 1);
            #pragma unroll
            for (int m = 0; m < 2; ++m) {
                int r0 = 16 * m + gid;
                float2 s0 = *(float2*)(Os + r0 * DDIM + col);
                float2 s1 = *(float2*)(Os + (r0 + 8) * DDIM + col);
                *(float2*)(og + (size_t)r0 * DDIM + col) =
                    make_float2(oacc[m][t][0] + s0.x + bb0, oacc[m][t][1] + s0.y + bb1);
                *(float2*)(og + (size_t)(r0 + 8) * DDIM + col) =
                    make_float2(oacc[m][t][2] + s1.x + bb0, oacc[m][t][3] + s1.y + bb1);
            }
        }
    }
}

extern "C" void kernel_launch(void* const* d_in, const int* in_sizes, int n_in,
                              void* d_out, int out_size) {
    (void)in_sizes; (void)n_in; (void)out_size;
    const float* X  = (const float*)d_in[0];   // [128,32,256]
    const float* W1 = (const float*)d_in[1];   // [256,1024]
    const float* b1 = (const float*)d_in[2];   // [1024]
    const float* W2 = (const float*)d_in[3];   // [1024,256]
    const float* b2 = (const float*)d_in[4];   // [256]
    float* out = (float*)d_out;                // [128,32,256]

    cudaFuncSetAttribute(fused_pair_mlp_fp16,
                         cudaFuncAttributeMaxDynamicSharedMemorySize, SMEM_TOTAL);
    fused_pair_mlp_fp16<<<128, THREADS, SMEM_TOTAL>>>(X, W1, b1, W2, b2, out);
}